// round 1
// baseline (speedup 1.0000x reference)
#include <cuda_runtime.h>

// Problem constants
#define D_MODEL 512
static constexpr float INT64_MAX_F = 9.2233720368547758e18f;

// digamma for x >= 1 (our args are z^2+1 >= 1): shift to x>=6, asymptotic series.
__device__ __forceinline__ float digamma_f(float x) {
    float r = 0.0f;
    // x >= 1, so at most 5 shifts reach x >= 6
    #pragma unroll
    for (int k = 0; k < 5; k++) {
        if (x < 6.0f) { r -= 1.0f / x; x += 1.0f; }
    }
    float inv  = 1.0f / x;
    float inv2 = inv * inv;
    // psi(x) ~ ln x - 1/(2x) - 1/(12x^2) + 1/(120x^4) - 1/(252x^6)
    float series = inv2 * (1.0f/12.0f - inv2 * (1.0f/120.0f - inv2 * (1.0f/252.0f)));
    return r + logf(x) - 0.5f * inv - series;
}

__global__ void __launch_bounds__(256)
cah_kernel(const float* __restrict__ x,
           const int*   __restrict__ actors,
           const float* __restrict__ w,
           const float* __restrict__ bvec,
           const int*   __restrict__ prev,
           float*       __restrict__ out,
           int n_actors)
{
    const int lane   = threadIdx.x & 31;
    const int warp   = (blockIdx.x * blockDim.x + threadIdx.x) >> 5;
    const int nwarps = (gridDim.x * blockDim.x) >> 5;

    // Preload w rows into registers: lane covers columns j*128 + lane*4 (float4)
    float4 w0r[4], w1r[4];
    #pragma unroll
    for (int j = 0; j < 4; j++) {
        int c = j * 128 + lane * 4;
        w0r[j] = *reinterpret_cast<const float4*>(w + c);
        w1r[j] = *reinterpret_cast<const float4*>(w + D_MODEL + c);
    }
    const float b0 = bvec[0];
    const float b1 = bvec[1];

    for (int i = warp; i < n_actors; i += nwarps) {
        const int row = __ldg(actors + i);
        const float4* xr = reinterpret_cast<const float4*>(x + (size_t)row * D_MODEL);

        // 4 independent 16B loads per lane -> full 2KB row per warp, coalesced
        float4 v[4];
        #pragma unroll
        for (int j = 0; j < 4; j++) v[j] = __ldg(xr + j * 32 + lane);

        float s0 = 0.0f, s1 = 0.0f;
        #pragma unroll
        for (int j = 0; j < 4; j++) {
            s0 = fmaf(v[j].x, w0r[j].x, s0); s0 = fmaf(v[j].y, w0r[j].y, s0);
            s0 = fmaf(v[j].z, w0r[j].z, s0); s0 = fmaf(v[j].w, w0r[j].w, s0);
            s1 = fmaf(v[j].x, w1r[j].x, s1); s1 = fmaf(v[j].y, w1r[j].y, s1);
            s1 = fmaf(v[j].z, w1r[j].z, s1); s1 = fmaf(v[j].w, w1r[j].w, s1);
        }

        // warp butterfly reduction
        #pragma unroll
        for (int off = 16; off > 0; off >>= 1) {
            s0 += __shfl_xor_sync(0xffffffffu, s0, off);
            s1 += __shfl_xor_sync(0xffffffffu, s1, off);
        }

        if (lane == 0) {
            const float z0 = s0 + b0;
            const float z1 = s1 + b1;
            const float a  = fmaf(z0, z0, 1.0f);
            const float bb = fmaf(z1, z1, 1.0f);

            const float pa     = (float)__ldg(prev + i);
            const float action = pa * (1.0f / INT64_MAX_F);

            const float lga   = lgammaf(a);
            const float lgb   = lgammaf(bb);
            const float lgab  = lgammaf(a + bb);
            const float lbeta = lga + lgb - lgab;

            const float logprob = (a - 1.0f) * logf(action)
                                + (bb - 1.0f) * log1pf(-action)
                                - lbeta;

            const float ent = lbeta
                            - (a - 1.0f)  * digamma_f(a)
                            - (bb - 1.0f) * digamma_f(bb)
                            + (a + bb - 2.0f) * digamma_f(a + bb);

            out[i]                    = action * INT64_MAX_F;  // action_return
            out[n_actors + i]         = logprob;
            out[2 * n_actors + i]     = ent;
            out[3 * n_actors + 2*i]   = a;                     // logits[:,0]
            out[3 * n_actors + 2*i+1] = bb;                    // logits[:,1]
        }
    }
}

extern "C" void kernel_launch(void* const* d_in, const int* in_sizes, int n_in,
                              void* d_out, int out_size)
{
    const float* x      = (const float*)d_in[0];
    const int*   actors = (const int*)  d_in[1];
    const float* w      = (const float*)d_in[2];
    const float* bvec   = (const float*)d_in[3];
    const int*   prev   = (const int*)  d_in[4];
    float*       out    = (float*)d_out;

    const int n_actors = in_sizes[1];  // 262144

    // 8 actors per warp: 32768 warps -> 4096 blocks of 256 threads
    const int threads = 256;
    const int blocks  = 4096;
    cah_kernel<<<blocks, threads>>>(x, actors, w, bvec, prev, out, n_actors);
}

// round 2
// speedup vs baseline: 1.9680x; 1.9680x over previous
#include <cuda_runtime.h>

#define D_MODEL 512
static constexpr float INT64_MAX_F = 9.2233720368547758e18f;

// digamma for x >= 1: shift to x >= 6, then asymptotic series.
__device__ __forceinline__ float digamma_f(float x) {
    float r = 0.0f;
    #pragma unroll
    for (int k = 0; k < 5; k++) {
        if (x < 6.0f) { r -= 1.0f / x; x += 1.0f; }
    }
    float inv  = 1.0f / x;
    float inv2 = inv * inv;
    float series = inv2 * (1.0f/12.0f - inv2 * (1.0f/120.0f - inv2 * (1.0f/252.0f)));
    return r + logf(x) - 0.5f * inv - series;
}

// ---------------------------------------------------------------------------
// Kernel A: gather + dual dot product. One warp handles 2 actors per pass.
// Writes a = z0^2+1, bb = z1^2+1 into the logits region of out.
// ---------------------------------------------------------------------------
__global__ void __launch_bounds__(256)
cah_gemv_kernel(const float* __restrict__ x,
                const int*   __restrict__ actors,
                const float* __restrict__ w,
                const float* __restrict__ bvec,
                float*       __restrict__ out,
                int n_actors)
{
    const int lane = threadIdx.x & 31;
    const int warp = (blockIdx.x * blockDim.x + threadIdx.x) >> 5;

    // Preload w into registers: lane covers columns j*128 + lane*4
    float4 w0r[4], w1r[4];
    #pragma unroll
    for (int j = 0; j < 4; j++) {
        int c = j * 128 + lane * 4;
        w0r[j] = *reinterpret_cast<const float4*>(w + c);
        w1r[j] = *reinterpret_cast<const float4*>(w + D_MODEL + c);
    }
    const float b0 = bvec[0];
    const float b1 = bvec[1];

    const int i0 = warp * 2;
    const int i1 = i0 + 1;
    if (i0 >= n_actors) return;
    const bool have2 = (i1 < n_actors);

    const int rowA = __ldg(actors + i0);
    const int rowB = have2 ? __ldg(actors + i1) : rowA;
    const float4* xa = reinterpret_cast<const float4*>(x + (size_t)rowA * D_MODEL);
    const float4* xb = reinterpret_cast<const float4*>(x + (size_t)rowB * D_MODEL);

    // 8 independent 16B loads per lane, all issued before use
    float4 va[4], vb[4];
    #pragma unroll
    for (int j = 0; j < 4; j++) va[j] = __ldg(xa + j * 32 + lane);
    #pragma unroll
    for (int j = 0; j < 4; j++) vb[j] = __ldg(xb + j * 32 + lane);

    float a0 = 0.0f, a1 = 0.0f, c0 = 0.0f, c1 = 0.0f;
    #pragma unroll
    for (int j = 0; j < 4; j++) {
        a0 = fmaf(va[j].x, w0r[j].x, a0); a0 = fmaf(va[j].y, w0r[j].y, a0);
        a0 = fmaf(va[j].z, w0r[j].z, a0); a0 = fmaf(va[j].w, w0r[j].w, a0);
        a1 = fmaf(va[j].x, w1r[j].x, a1); a1 = fmaf(va[j].y, w1r[j].y, a1);
        a1 = fmaf(va[j].z, w1r[j].z, a1); a1 = fmaf(va[j].w, w1r[j].w, a1);
        c0 = fmaf(vb[j].x, w0r[j].x, c0); c0 = fmaf(vb[j].y, w0r[j].y, c0);
        c0 = fmaf(vb[j].z, w0r[j].z, c0); c0 = fmaf(vb[j].w, w0r[j].w, c0);
        c1 = fmaf(vb[j].x, w1r[j].x, c1); c1 = fmaf(vb[j].y, w1r[j].y, c1);
        c1 = fmaf(vb[j].z, w1r[j].z, c1); c1 = fmaf(vb[j].w, w1r[j].w, c1);
    }

    #pragma unroll
    for (int off = 16; off > 0; off >>= 1) {
        a0 += __shfl_xor_sync(0xffffffffu, a0, off);
        a1 += __shfl_xor_sync(0xffffffffu, a1, off);
        c0 += __shfl_xor_sync(0xffffffffu, c0, off);
        c1 += __shfl_xor_sync(0xffffffffu, c1, off);
    }

    if (lane == 0) {
        const float za0 = a0 + b0, za1 = a1 + b1;
        float2 la; la.x = fmaf(za0, za0, 1.0f); la.y = fmaf(za1, za1, 1.0f);
        *reinterpret_cast<float2*>(out + 3 * (size_t)n_actors + 2 * (size_t)i0) = la;
        if (have2) {
            const float zb0 = c0 + b0, zb1 = c1 + b1;
            float2 lb; lb.x = fmaf(zb0, zb0, 1.0f); lb.y = fmaf(zb1, zb1, 1.0f);
            *reinterpret_cast<float2*>(out + 3 * (size_t)n_actors + 2 * (size_t)i1) = lb;
        }
    }
}

// ---------------------------------------------------------------------------
// Kernel B: fully parallel epilogue. One thread per actor.
// Reads a,bb back from logits region; writes action_return/logprob/entropy.
// ---------------------------------------------------------------------------
__global__ void __launch_bounds__(256)
cah_epilogue_kernel(const int* __restrict__ prev,
                    float*     __restrict__ out,
                    int n_actors)
{
    const int i = blockIdx.x * blockDim.x + threadIdx.x;
    if (i >= n_actors) return;

    const float2 l = *reinterpret_cast<const float2*>(out + 3 * (size_t)n_actors + 2 * (size_t)i);
    const float a  = l.x;
    const float bb = l.y;

    const float pa     = (float)__ldg(prev + i);
    const float action = pa * (1.0f / INT64_MAX_F);

    const float lbeta = lgammaf(a) + lgammaf(bb) - lgammaf(a + bb);

    const float logprob = (a - 1.0f) * logf(action)
                        + (bb - 1.0f) * log1pf(-action)
                        - lbeta;

    const float ent = lbeta
                    - (a - 1.0f)  * digamma_f(a)
                    - (bb - 1.0f) * digamma_f(bb)
                    + (a + bb - 2.0f) * digamma_f(a + bb);

    out[i]                        = action * INT64_MAX_F;
    out[(size_t)n_actors + i]     = logprob;
    out[2 * (size_t)n_actors + i] = ent;
}

extern "C" void kernel_launch(void* const* d_in, const int* in_sizes, int n_in,
                              void* d_out, int out_size)
{
    const float* x      = (const float*)d_in[0];
    const int*   actors = (const int*)  d_in[1];
    const float* w      = (const float*)d_in[2];
    const float* bvec   = (const float*)d_in[3];
    const int*   prev   = (const int*)  d_in[4];
    float*       out    = (float*)d_out;

    const int n_actors = in_sizes[1];  // 262144

    // Kernel A: 2 actors per warp -> n_actors/2 warps
    const int warpsA   = (n_actors + 1) / 2;
    const int threadsA = 256;
    const int blocksA  = (warpsA * 32 + threadsA - 1) / threadsA;
    cah_gemv_kernel<<<blocksA, threadsA>>>(x, actors, w, bvec, out, n_actors);

    // Kernel B: 1 thread per actor
    const int threadsB = 256;
    const int blocksB  = (n_actors + threadsB - 1) / threadsB;
    cah_epilogue_kernel<<<blocksB, threadsB>>>(prev, out, n_actors);
}

// round 3
// speedup vs baseline: 2.0640x; 1.0488x over previous
#include <cuda_runtime.h>

#define D_MODEL 512
static constexpr float INT64_MAX_F = 9.2233720368547758e18f;

// ---------------------------------------------------------------------------
// Fused lgamma + digamma for t in [1, ~9] (our args: a,b in [1,~2.5], a+b in
// [2,~5]). Shift by exactly 4 (y = t+4 >= 5), asymptotic series, with the
// recurrence product t(t+1)(t+2)(t+3) = u(u+2), u = t^2+3t, shared between
// the lgamma downshift and the digamma rational term.
// ---------------------------------------------------------------------------
__device__ __forceinline__ void lgamma_digamma(float t, float& lg, float& dg) {
    const float u = t * (t + 3.0f);          // t^2 + 3t
    const float d = u * (u + 2.0f);          // t(t+1)(t+2)(t+3)
    const float y = t + 4.0f;
    const float ln_y  = logf(y);
    const float inv_y = __fdividef(1.0f, y);
    const float inv2  = inv_y * inv_y;
    const float inv_d = __fdividef(1.0f, d);
    // r = 1/t + 1/(t+1) + 1/(t+2) + 1/(t+3) = (2t+3)(2u+2)/(u(u+2))
    const float r    = (2.0f * t + 3.0f) * (2.0f * u + 2.0f) * inv_d;
    const float ln_p = logf(d);

    // lgamma(t) = stirling(y) - ln(product)
    lg = fmaf(y - 0.5f, ln_y, -y) + 0.918938533204672742f   // 0.5*ln(2*pi)
       + inv_y * (0.0833333333333f - inv2 * (0.00277777777778f - inv2 * 0.000793650793651f))
       - ln_p;
    // digamma(t) = psi(y) - r
    dg = ln_y - 0.5f * inv_y
       - inv2 * (0.0833333333333f - inv2 * (0.00833333333333f - inv2 * 0.00396825396825f))
       - r;
}

// ---------------------------------------------------------------------------
// Kernel A: gather + dual dot product. One warp handles 4 actors.
// 16 independent float4 gathers in flight per lane. Writes logits (a,bb)
// pairs with two float4 stores per warp.
// ---------------------------------------------------------------------------
__global__ void __launch_bounds__(256)
cah_gemv_kernel(const float* __restrict__ x,
                const int*   __restrict__ actors,
                const float* __restrict__ w,
                const float* __restrict__ bvec,
                float*       __restrict__ out,
                int n_actors)
{
    const int lane = threadIdx.x & 31;
    const int warp = (blockIdx.x * blockDim.x + threadIdx.x) >> 5;

    const int i0 = warp * 4;
    if (i0 >= n_actors) return;

    // Preload w into registers: lane covers columns j*128 + lane*4
    float4 w0r[4], w1r[4];
    #pragma unroll
    for (int j = 0; j < 4; j++) {
        int c = j * 128 + lane * 4;
        w0r[j] = *reinterpret_cast<const float4*>(w + c);
        w1r[j] = *reinterpret_cast<const float4*>(w + D_MODEL + c);
    }
    const float b0 = bvec[0];
    const float b1 = bvec[1];

    // Row pointers for the 4 actors (n_actors is a multiple of 4: 262144)
    const float4* xr[4];
    #pragma unroll
    for (int q = 0; q < 4; q++) {
        const int idx = (i0 + q < n_actors) ? (i0 + q) : i0;
        const int row = __ldg(actors + idx);
        xr[q] = reinterpret_cast<const float4*>(x + (size_t)row * D_MODEL);
    }

    // 16 independent 16B gathers per lane, all issued before any use
    float4 v[4][4];
    #pragma unroll
    for (int q = 0; q < 4; q++)
        #pragma unroll
        for (int j = 0; j < 4; j++)
            v[q][j] = __ldg(xr[q] + j * 32 + lane);

    float acc[4][2];
    #pragma unroll
    for (int q = 0; q < 4; q++) {
        float s0 = 0.0f, s1 = 0.0f;
        #pragma unroll
        for (int j = 0; j < 4; j++) {
            s0 = fmaf(v[q][j].x, w0r[j].x, s0); s0 = fmaf(v[q][j].y, w0r[j].y, s0);
            s0 = fmaf(v[q][j].z, w0r[j].z, s0); s0 = fmaf(v[q][j].w, w0r[j].w, s0);
            s1 = fmaf(v[q][j].x, w1r[j].x, s1); s1 = fmaf(v[q][j].y, w1r[j].y, s1);
            s1 = fmaf(v[q][j].z, w1r[j].z, s1); s1 = fmaf(v[q][j].w, w1r[j].w, s1);
        }
        acc[q][0] = s0; acc[q][1] = s1;
    }

    // Butterfly-reduce all 8 partial sums
    #pragma unroll
    for (int off = 16; off > 0; off >>= 1) {
        #pragma unroll
        for (int q = 0; q < 4; q++) {
            acc[q][0] += __shfl_xor_sync(0xffffffffu, acc[q][0], off);
            acc[q][1] += __shfl_xor_sync(0xffffffffu, acc[q][1], off);
        }
    }

    if (lane == 0) {
        float lg[8];
        #pragma unroll
        for (int q = 0; q < 4; q++) {
            const float z0 = acc[q][0] + b0;
            const float z1 = acc[q][1] + b1;
            lg[2*q]   = fmaf(z0, z0, 1.0f);
            lg[2*q+1] = fmaf(z1, z1, 1.0f);
        }
        float* lbase = out + 3 * (size_t)n_actors + 2 * (size_t)i0;
        if (i0 + 3 < n_actors) {
            *reinterpret_cast<float4*>(lbase)     = make_float4(lg[0], lg[1], lg[2], lg[3]);
            *reinterpret_cast<float4*>(lbase + 4) = make_float4(lg[4], lg[5], lg[6], lg[7]);
        } else {
            for (int q = 0; q < 4 && i0 + q < n_actors; q++) {
                lbase[2*q]   = lg[2*q];
                lbase[2*q+1] = lg[2*q+1];
            }
        }
    }
}

// ---------------------------------------------------------------------------
// Kernel B: fully parallel epilogue. One thread per actor.
// ---------------------------------------------------------------------------
__global__ void __launch_bounds__(256)
cah_epilogue_kernel(const int* __restrict__ prev,
                    float*     __restrict__ out,
                    int n_actors)
{
    const int i = blockIdx.x * blockDim.x + threadIdx.x;
    if (i >= n_actors) return;

    const float2 l = *reinterpret_cast<const float2*>(out + 3 * (size_t)n_actors + 2 * (size_t)i);
    const float a  = l.x;
    const float bb = l.y;

    const float pa     = (float)__ldg(prev + i);
    const float action = pa * (1.0f / INT64_MAX_F);

    float lga, dga, lgb, dgb, lgab, dgab;
    lgamma_digamma(a,      lga,  dga);
    lgamma_digamma(bb,     lgb,  dgb);
    lgamma_digamma(a + bb, lgab, dgab);

    const float lbeta = lga + lgb - lgab;

    const float logprob = (a - 1.0f) * logf(action)
                        + (bb - 1.0f) * log1pf(-action)
                        - lbeta;

    const float ent = lbeta
                    - (a - 1.0f)  * dga
                    - (bb - 1.0f) * dgb
                    + (a + bb - 2.0f) * dgab;

    out[i]                        = action * INT64_MAX_F;
    out[(size_t)n_actors + i]     = logprob;
    out[2 * (size_t)n_actors + i] = ent;
}

extern "C" void kernel_launch(void* const* d_in, const int* in_sizes, int n_in,
                              void* d_out, int out_size)
{
    const float* x      = (const float*)d_in[0];
    const int*   actors = (const int*)  d_in[1];
    const float* w      = (const float*)d_in[2];
    const float* bvec   = (const float*)d_in[3];
    const int*   prev   = (const int*)  d_in[4];
    float*       out    = (float*)d_out;

    const int n_actors = in_sizes[1];  // 262144

    // Kernel A: 4 actors per warp
    const int warpsA   = (n_actors + 3) / 4;
    const int threadsA = 256;
    const int blocksA  = (warpsA * 32 + threadsA - 1) / threadsA;
    cah_gemv_kernel<<<blocksA, threadsA>>>(x, actors, w, bvec, out, n_actors);

    // Kernel B: 1 thread per actor
    const int threadsB = 256;
    const int blocksB  = (n_actors + threadsB - 1) / threadsB;
    cah_epilogue_kernel<<<blocksB, threadsB>>>(prev, out, n_actors);
}

// round 4
// speedup vs baseline: 2.0715x; 1.0036x over previous
#include <cuda_runtime.h>

#define D_MODEL 512
static constexpr float INT64_MAX_F = 9.2233720368547758e18f;

// ---------------------------------------------------------------------------
// Fused lgamma + digamma for t in [1, ~9] (our args: a,b in [1,~2.5], a+b in
// [2,~5]). Shift by exactly 4 (y = t+4 >= 5), asymptotic series, with the
// recurrence product t(t+1)(t+2)(t+3) = u(u+2), u = t^2+3t, shared between
// the lgamma downshift and the digamma rational term.
// ---------------------------------------------------------------------------
__device__ __forceinline__ void lgamma_digamma(float t, float& lg, float& dg) {
    const float u = t * (t + 3.0f);          // t^2 + 3t
    const float d = u * (u + 2.0f);          // t(t+1)(t+2)(t+3)
    const float y = t + 4.0f;
    const float ln_y  = logf(y);
    const float inv_y = __fdividef(1.0f, y);
    const float inv2  = inv_y * inv_y;
    const float inv_d = __fdividef(1.0f, d);
    // r = 1/t + 1/(t+1) + 1/(t+2) + 1/(t+3) = (2t+3)(2u+2)/(u(u+2))
    const float r    = (2.0f * t + 3.0f) * (2.0f * u + 2.0f) * inv_d;
    const float ln_p = logf(d);

    // lgamma(t) = stirling(y) - ln(product)
    lg = fmaf(y - 0.5f, ln_y, -y) + 0.918938533204672742f   // 0.5*ln(2*pi)
       + inv_y * (0.0833333333333f - inv2 * (0.00277777777778f - inv2 * 0.000793650793651f))
       - ln_p;
    // digamma(t) = psi(y) - r
    dg = ln_y - 0.5f * inv_y
       - inv2 * (0.0833333333333f - inv2 * (0.00833333333333f - inv2 * 0.00396825396825f))
       - r;
}

// ---------------------------------------------------------------------------
// Kernel A: gather + dual dot product. One warp handles 4 actors.
// 16 independent float4 gathers in flight per lane. Writes logits (a,bb)
// pairs with two float4 stores per warp.
// ---------------------------------------------------------------------------
__global__ void __launch_bounds__(256)
cah_gemv_kernel(const float* __restrict__ x,
                const int*   __restrict__ actors,
                const float* __restrict__ w,
                const float* __restrict__ bvec,
                float*       __restrict__ out,
                int n_actors)
{
    const int lane = threadIdx.x & 31;
    const int warp = (blockIdx.x * blockDim.x + threadIdx.x) >> 5;

    const int i0 = warp * 4;
    if (i0 >= n_actors) return;

    // Preload w into registers: lane covers columns j*128 + lane*4
    float4 w0r[4], w1r[4];
    #pragma unroll
    for (int j = 0; j < 4; j++) {
        int c = j * 128 + lane * 4;
        w0r[j] = *reinterpret_cast<const float4*>(w + c);
        w1r[j] = *reinterpret_cast<const float4*>(w + D_MODEL + c);
    }
    const float b0 = bvec[0];
    const float b1 = bvec[1];

    // Row pointers for the 4 actors (n_actors is a multiple of 4: 262144)
    const float4* xr[4];
    #pragma unroll
    for (int q = 0; q < 4; q++) {
        const int idx = (i0 + q < n_actors) ? (i0 + q) : i0;
        const int row = __ldg(actors + idx);
        xr[q] = reinterpret_cast<const float4*>(x + (size_t)row * D_MODEL);
    }

    // 16 independent 16B gathers per lane, all issued before any use
    float4 v[4][4];
    #pragma unroll
    for (int q = 0; q < 4; q++)
        #pragma unroll
        for (int j = 0; j < 4; j++)
            v[q][j] = __ldg(xr[q] + j * 32 + lane);

    float acc[4][2];
    #pragma unroll
    for (int q = 0; q < 4; q++) {
        float s0 = 0.0f, s1 = 0.0f;
        #pragma unroll
        for (int j = 0; j < 4; j++) {
            s0 = fmaf(v[q][j].x, w0r[j].x, s0); s0 = fmaf(v[q][j].y, w0r[j].y, s0);
            s0 = fmaf(v[q][j].z, w0r[j].z, s0); s0 = fmaf(v[q][j].w, w0r[j].w, s0);
            s1 = fmaf(v[q][j].x, w1r[j].x, s1); s1 = fmaf(v[q][j].y, w1r[j].y, s1);
            s1 = fmaf(v[q][j].z, w1r[j].z, s1); s1 = fmaf(v[q][j].w, w1r[j].w, s1);
        }
        acc[q][0] = s0; acc[q][1] = s1;
    }

    // Butterfly-reduce all 8 partial sums
    #pragma unroll
    for (int off = 16; off > 0; off >>= 1) {
        #pragma unroll
        for (int q = 0; q < 4; q++) {
            acc[q][0] += __shfl_xor_sync(0xffffffffu, acc[q][0], off);
            acc[q][1] += __shfl_xor_sync(0xffffffffu, acc[q][1], off);
        }
    }

    if (lane == 0) {
        float lg[8];
        #pragma unroll
        for (int q = 0; q < 4; q++) {
            const float z0 = acc[q][0] + b0;
            const float z1 = acc[q][1] + b1;
            lg[2*q]   = fmaf(z0, z0, 1.0f);
            lg[2*q+1] = fmaf(z1, z1, 1.0f);
        }
        float* lbase = out + 3 * (size_t)n_actors + 2 * (size_t)i0;
        if (i0 + 3 < n_actors) {
            *reinterpret_cast<float4*>(lbase)     = make_float4(lg[0], lg[1], lg[2], lg[3]);
            *reinterpret_cast<float4*>(lbase + 4) = make_float4(lg[4], lg[5], lg[6], lg[7]);
        } else {
            for (int q = 0; q < 4 && i0 + q < n_actors; q++) {
                lbase[2*q]   = lg[2*q];
                lbase[2*q+1] = lg[2*q+1];
            }
        }
    }
}

// ---------------------------------------------------------------------------
// Kernel B: fully parallel epilogue. One thread per actor.
// ---------------------------------------------------------------------------
__global__ void __launch_bounds__(256)
cah_epilogue_kernel(const int* __restrict__ prev,
                    float*     __restrict__ out,
                    int n_actors)
{
    const int i = blockIdx.x * blockDim.x + threadIdx.x;
    if (i >= n_actors) return;

    const float2 l = *reinterpret_cast<const float2*>(out + 3 * (size_t)n_actors + 2 * (size_t)i);
    const float a  = l.x;
    const float bb = l.y;

    const float pa     = (float)__ldg(prev + i);
    const float action = pa * (1.0f / INT64_MAX_F);

    float lga, dga, lgb, dgb, lgab, dgab;
    lgamma_digamma(a,      lga,  dga);
    lgamma_digamma(bb,     lgb,  dgb);
    lgamma_digamma(a + bb, lgab, dgab);

    const float lbeta = lga + lgb - lgab;

    const float logprob = (a - 1.0f) * logf(action)
                        + (bb - 1.0f) * log1pf(-action)
                        - lbeta;

    const float ent = lbeta
                    - (a - 1.0f)  * dga
                    - (bb - 1.0f) * dgb
                    + (a + bb - 2.0f) * dgab;

    out[i]                        = action * INT64_MAX_F;
    out[(size_t)n_actors + i]     = logprob;
    out[2 * (size_t)n_actors + i] = ent;
}

extern "C" void kernel_launch(void* const* d_in, const int* in_sizes, int n_in,
                              void* d_out, int out_size)
{
    const float* x      = (const float*)d_in[0];
    const int*   actors = (const int*)  d_in[1];
    const float* w      = (const float*)d_in[2];
    const float* bvec   = (const float*)d_in[3];
    const int*   prev   = (const int*)  d_in[4];
    float*       out    = (float*)d_out;

    const int n_actors = in_sizes[1];  // 262144

    // Kernel A: 4 actors per warp
    const int warpsA   = (n_actors + 3) / 4;
    const int threadsA = 256;
    const int blocksA  = (warpsA * 32 + threadsA - 1) / threadsA;
    cah_gemv_kernel<<<blocksA, threadsA>>>(x, actors, w, bvec, out, n_actors);

    // Kernel B: 1 thread per actor
    const int threadsB = 256;
    const int blocksB  = (n_actors + threadsB - 1) / threadsB;
    cah_epilogue_kernel<<<blocksB, threadsB>>>(prev, out, n_actors);
}